// round 14
// baseline (speedup 1.0000x reference)
#include <cuda_runtime.h>
#include <cuda_fp16.h>
#include <cstdint>

// Problem constants
#define B_  2
#define S_  2048
#define D_  1024
#define H_  16
#define HD_ 64
#define M_  (B_ * S_)   // 4096

// Scratch (allocation-free rule: __device__ globals)
__device__ __half g_xh[(size_t)M_ * D_];
__device__ __half g_wqkvh[(size_t)3 * D_ * D_];
__device__ __half g_wprojh[(size_t)D_ * D_];
__device__ __half g_qkvh[(size_t)3 * B_ * H_ * S_ * HD_];  // [3][B][H][S][hd]
__device__ __half g_attnh[(size_t)M_ * D_];

// ---------------------------------------------------------------------------
// helpers
// ---------------------------------------------------------------------------
__device__ __forceinline__ unsigned smem_u32(const void* p) {
    return (unsigned)__cvta_generic_to_shared(p);
}
__device__ __forceinline__ void cp_async16(unsigned dst, const void* src) {
    asm volatile("cp.async.cg.shared.global [%0], [%1], 16;\n" :: "r"(dst), "l"(src));
}
__device__ __forceinline__ void cp_commit() {
    asm volatile("cp.async.commit_group;\n");
}
template<int N>
__device__ __forceinline__ void cp_wait() {
    asm volatile("cp.async.wait_group %0;\n" :: "n"(N));
}
__device__ __forceinline__ void ldsm4(unsigned& r0, unsigned& r1, unsigned& r2,
                                      unsigned& r3, unsigned a) {
    asm volatile("ldmatrix.sync.aligned.m8n8.x4.shared.b16 {%0,%1,%2,%3},[%4];"
                 : "=r"(r0), "=r"(r1), "=r"(r2), "=r"(r3) : "r"(a));
}
__device__ __forceinline__ void ldsm4t(unsigned& r0, unsigned& r1, unsigned& r2,
                                       unsigned& r3, unsigned a) {
    asm volatile("ldmatrix.sync.aligned.m8n8.x4.trans.shared.b16 {%0,%1,%2,%3},[%4];"
                 : "=r"(r0), "=r"(r1), "=r"(r2), "=r"(r3) : "r"(a));
}
__device__ __forceinline__ void mma16816(float* c, const unsigned* a, const unsigned* b) {
    asm volatile("mma.sync.aligned.m16n8k16.row.col.f32.f16.f16.f32 "
                 "{%0,%1,%2,%3},{%4,%5,%6,%7},{%8,%9},{%0,%1,%2,%3};"
                 : "+f"(c[0]), "+f"(c[1]), "+f"(c[2]), "+f"(c[3])
                 : "r"(a[0]), "r"(a[1]), "r"(a[2]), "r"(a[3]), "r"(b[0]), "r"(b[1]));
}
// fp16-accumulator variant (2 regs: c[0]=row g, c[1]=row g+8, cols 2tg/2tg+1)
__device__ __forceinline__ void mma16816h(unsigned* c, const unsigned* a, const unsigned* b) {
    asm volatile("mma.sync.aligned.m16n8k16.row.col.f16.f16.f16.f16 "
                 "{%0,%1},{%2,%3,%4,%5},{%6,%7},{%0,%1};"
                 : "+r"(c[0]), "+r"(c[1])
                 : "r"(a[0]), "r"(a[1]), "r"(a[2]), "r"(a[3]), "r"(b[0]), "r"(b[1]));
}

// ---------------------------------------------------------------------------
// fp32 -> fp16 convert: one launch for all three tensors
// ---------------------------------------------------------------------------
#define N1_ (M_ * D_)          // x
#define N2_ (3 * D_ * D_)      // w_qkv
#define N3_ (D_ * D_)          // w_proj

__global__ void cvt_all(const float* __restrict__ x,
                        const float* __restrict__ wq,
                        const float* __restrict__ wp) {
    const int i = (blockIdx.x * blockDim.x + threadIdx.x) * 4;
    const float* src;
    __half* dst;
    int off;
    if (i < N1_)            { src = x;  dst = g_xh;     off = i; }
    else if (i < N1_ + N2_) { src = wq; dst = g_wqkvh;  off = i - N1_; }
    else                    { src = wp; dst = g_wprojh; off = i - N1_ - N2_; }
    float4 v = *(const float4*)(src + off);
    *(__half2*)(dst + off)     = __floats2half2_rn(v.x, v.y);
    *(__half2*)(dst + off + 2) = __floats2half2_rn(v.z, v.w);
}

// ---------------------------------------------------------------------------
// fp16 mma.sync GEMM (round-12 best, unchanged): BK=64, 2-stage ring,
// 128 threads (4 warps 2x2).
// gemm1: BM=128, 3 CTAs/SM. proj: BM=64, 4 CTAs/SM.
// ---------------------------------------------------------------------------
#define GST 72                           // smem row stride in halves (64 + 8)
#define GABUF(BM_) ((BM_) * GST * 2)     // A bytes per stage
#define GBBUF (128 * GST * 2)            // B bytes per stage
#define GSMEM(BM_, ST_) ((ST_) * (GABUF(BM_) + GBBUF))

template<int SCATTER, int BM_, int STAGES_, int MINB_>
__global__ __launch_bounds__(128, MINB_)
void gemm_h(const __half* __restrict__ Ain, const __half* __restrict__ W,
            const float* __restrict__ bias, float* __restrict__ C,
            int N, int K)
{
    extern __shared__ char dsm[];
    const __half* A = Ain ? Ain : g_attnh;
    constexpr int MI = BM_ / 32;         // m16 groups per warp (4 or 2)
    constexpr int PF = STAGES_ - 1;      // prefetch distance

    const int tid = threadIdx.x;
    const int lane = tid & 31, warp = tid >> 5;
    const int wm = warp & 1, wn = warp >> 1;
    const int g = lane >> 2, tg = lane & 3;
    const int m0 = blockIdx.y * BM_, n0 = blockIdx.x * 128;

    const unsigned sA = smem_u32(dsm);
    const unsigned sB = sA + STAGES_ * GABUF(BM_);

    const int ra = (lane & 7) + 8 * ((lane >> 3) & 1);
    const int ka = 8 * (lane >> 4);
    const int rb = (lane & 7) + 8 * (lane >> 4);
    const int kb = 8 * ((lane >> 3) & 1);

    float acc[MI][8][4];
#pragma unroll
    for (int mi = 0; mi < MI; mi++)
#pragma unroll
        for (int ni = 0; ni < 8; ni++)
#pragma unroll
            for (int c = 0; c < 4; c++) acc[mi][ni][c] = 0.0f;

    const __half* aA = A + (size_t)m0 * K;
    const __half* aW = W + (size_t)n0 * K;

    auto prefetch = [&](int it) {
        const int stg = it % STAGES_;
        const int k0 = it * 64;
#pragma unroll
        for (int i = 0; i < BM_ / 16; i++) {     // A: BM_ rows x 8 chunks
            const int c = tid + i * 128;
            const int row = c >> 3, q = c & 7;
            cp_async16(sA + stg * GABUF(BM_) + (row * GST + q * 8) * 2,
                       aA + (size_t)row * K + k0 + q * 8);
        }
#pragma unroll
        for (int i = 0; i < 8; i++) {            // B: 128 rows x 8 chunks
            const int c = tid + i * 128;
            const int row = c >> 3, q = c & 7;
            cp_async16(sB + stg * GBBUF + (row * GST + q * 8) * 2,
                       aW + (size_t)row * K + k0 + q * 8);
        }
        cp_commit();
    };

    const int T = K / 64;                // 16
#pragma unroll
    for (int i = 0; i < PF; i++) prefetch(i);

    for (int it = 0; it < T; it++) {
        cp_wait<PF - 1>();
        __syncthreads();
        if (it + PF < T) prefetch(it + PF); else cp_commit();

        const int stg = it % STAGES_;
#pragma unroll
        for (int ks = 0; ks < 4; ks++) {
            unsigned af[MI][4];
#pragma unroll
            for (int mi = 0; mi < MI; mi++) {
                const unsigned addr = sA + stg * GABUF(BM_) +
                    ((wm * (BM_ / 2) + mi * 16 + ra) * GST + ks * 16 + ka) * 2;
                ldsm4(af[mi][0], af[mi][1], af[mi][2], af[mi][3], addr);
            }
            unsigned bf[8][2];
#pragma unroll
            for (int ntp = 0; ntp < 4; ntp++) {
                unsigned r0, r1, r2, r3;
                const unsigned addr = sB + stg * GBBUF +
                    ((wn * 64 + ntp * 16 + rb) * GST + ks * 16 + kb) * 2;
                ldsm4(r0, r1, r2, r3, addr);
                bf[2 * ntp][0] = r0; bf[2 * ntp][1] = r1;
                bf[2 * ntp + 1][0] = r2; bf[2 * ntp + 1][1] = r3;
            }
#pragma unroll
            for (int mi = 0; mi < MI; mi++)
#pragma unroll
                for (int ni = 0; ni < 8; ni++)
                    mma16816(acc[mi][ni], af[mi], bf[ni]);
        }
    }

#pragma unroll
    for (int mi = 0; mi < MI; mi++) {
#pragma unroll
        for (int half = 0; half < 2; half++) {
            const int m = m0 + wm * (BM_ / 2) + mi * 16 + g + half * 8;
#pragma unroll
            for (int ni = 0; ni < 8; ni++) {
                const int n = n0 + wn * 64 + ni * 8 + 2 * tg;
                const float v0 = acc[mi][ni][half * 2 + 0] + bias[n];
                const float v1 = acc[mi][ni][half * 2 + 1] + bias[n + 1];
                if (SCATTER) {
                    const int three = n >> 10;
                    const int h = (n >> 6) & (H_ - 1);
                    const int d = n & (HD_ - 1);
                    const int b = m >> 11;
                    const int s = m & (S_ - 1);
                    *(__half2*)&g_qkvh[((size_t)three * (B_ * H_) + b * H_ + h) * (S_ * HD_)
                                       + (size_t)s * HD_ + d] = __floats2half2_rn(v0, v1);
                } else {
                    *(float2*)&C[(size_t)m * N + n] = make_float2(v0, v1);
                }
            }
        }
    }
}

// ---------------------------------------------------------------------------
// fp16 mma.sync flash attention, m32 warp tiles, Q in registers, fp16 QK
// accumulators + per-mi streaming softmax (reg cut -> 3 CTAs/SM).
// CTA = 128 queries x 1 (b,h); 4 warps x 32 q. 64-key tiles, 3-stage ring.
// grid = (S/128, B*H), block = 128.
// ---------------------------------------------------------------------------
#define AST 72
#define ABUF (64 * AST * 2)
#define ASTAGES 3
#define ASMEM (2 * ASTAGES * ABUF)
#define SCALE_LOG2E 0.1803368801111244f   // 0.125 * log2(e)

__global__ __launch_bounds__(128, 3)
void attn_h()
{
    extern __shared__ char dsm[];
    const int bh = blockIdx.y;
    const int q0 = blockIdx.x * 128;
    const int tid = threadIdx.x;
    const int warp = tid >> 5, lane = tid & 31;
    const int g = lane >> 2, tg = lane & 3;
    const int wq = warp * 32;

    const __half* Qp = g_qkvh + (size_t)bh * (S_ * HD_);
    const __half* Kp = g_qkvh + (size_t)(B_ * H_ + bh) * (S_ * HD_);
    const __half* Vp = g_qkvh + (size_t)(2 * B_ * H_ + bh) * (S_ * HD_);

    const unsigned sK = smem_u32(dsm);
    const unsigned sV = sK + ASTAGES * ABUF;

    // Q fragments: two m16 groups (mi), 4 k16-steps each (fp16, 32 regs)
    unsigned qa[2][4][4];
#pragma unroll
    for (int mi = 0; mi < 2; mi++) {
        const __half* Qr0 = Qp + (size_t)(q0 + wq + mi * 16 + g) * HD_;
        const __half* Qr1 = Qp + (size_t)(q0 + wq + mi * 16 + g + 8) * HD_;
#pragma unroll
        for (int ks = 0; ks < 4; ks++) {
            qa[mi][ks][0] = *(const unsigned*)(Qr0 + ks * 16 + 2 * tg);
            qa[mi][ks][1] = *(const unsigned*)(Qr1 + ks * 16 + 2 * tg);
            qa[mi][ks][2] = *(const unsigned*)(Qr0 + ks * 16 + 8 + 2 * tg);
            qa[mi][ks][3] = *(const unsigned*)(Qr1 + ks * 16 + 8 + 2 * tg);
        }
    }

    const int rkb = (lane & 7) + 8 * (lane >> 4);
    const int kkb = 8 * ((lane >> 3) & 1);
    const int rvb = (lane & 7) + 8 * ((lane >> 3) & 1);
    const int kvb = 8 * (lane >> 4);

    float o[2][8][4];
#pragma unroll
    for (int mi = 0; mi < 2; mi++)
#pragma unroll
        for (int ni = 0; ni < 8; ni++)
#pragma unroll
            for (int c = 0; c < 4; c++) o[mi][ni][c] = 0.0f;
    float mv0[2] = {-3.0e38f, -3.0e38f}, mv1[2] = {-3.0e38f, -3.0e38f};
    float lv0[2] = {0.0f, 0.0f},         lv1[2] = {0.0f, 0.0f};

    auto prefetch = [&](int it) {
        const int stg = it % ASTAGES;
        const int kt = it * 64;
#pragma unroll
        for (int i = 0; i < 4; i++) {
            const int c = tid + i * 128;
            const int row = c >> 3, q = c & 7;
            cp_async16(sK + stg * ABUF + (row * AST + q * 8) * 2,
                       Kp + (size_t)(kt + row) * HD_ + q * 8);
            cp_async16(sV + stg * ABUF + (row * AST + q * 8) * 2,
                       Vp + (size_t)(kt + row) * HD_ + q * 8);
        }
        cp_commit();
    };

    const int T = S_ / 64;   // 32
    prefetch(0); prefetch(1);

    for (int it = 0; it < T; it++) {
        cp_wait<1>();
        __syncthreads();
        if (it + 2 < T) prefetch(it + 2); else cp_commit();

        const int stg = it % ASTAGES;

        // S = Q K^T with fp16 accumulators (32 regs instead of 64)
        unsigned sch[2][8][2];
#pragma unroll
        for (int mi = 0; mi < 2; mi++)
#pragma unroll
            for (int ni = 0; ni < 8; ni++) {
                sch[mi][ni][0] = 0u; sch[mi][ni][1] = 0u;
            }
#pragma unroll
        for (int ks = 0; ks < 4; ks++) {
#pragma unroll
            for (int ntp = 0; ntp < 4; ntp++) {
                unsigned r0, r1, r2, r3;
                const unsigned addr = sK + stg * ABUF +
                    ((ntp * 16 + rkb) * AST + ks * 16 + kkb) * 2;
                ldsm4(r0, r1, r2, r3, addr);
                unsigned b0[2] = {r0, r1}, b1[2] = {r2, r3};
#pragma unroll
                for (int mi = 0; mi < 2; mi++) {
                    mma16816h(sch[mi][2 * ntp],     qa[mi][ks], b0);
                    mma16816h(sch[mi][2 * ntp + 1], qa[mi][ks], b1);
                }
            }
        }

        // streaming softmax: one mi group at a time (scf live per-group only)
        unsigned ph[2][8][2];
#pragma unroll
        for (int mi = 0; mi < 2; mi++) {
            float scf[8][4];
#pragma unroll
            for (int ni = 0; ni < 8; ni++) {
                const float2 lo = __half22float2(*(__half2*)&sch[mi][ni][0]);
                const float2 hi = __half22float2(*(__half2*)&sch[mi][ni][1]);
                scf[ni][0] = lo.x * SCALE_LOG2E;
                scf[ni][1] = lo.y * SCALE_LOG2E;
                scf[ni][2] = hi.x * SCALE_LOG2E;
                scf[ni][3] = hi.y * SCALE_LOG2E;
            }
            float mt0 = -3.0e38f, mt1 = -3.0e38f;
#pragma unroll
            for (int ni = 0; ni < 8; ni++) {
                mt0 = fmaxf(mt0, fmaxf(scf[ni][0], scf[ni][1]));
                mt1 = fmaxf(mt1, fmaxf(scf[ni][2], scf[ni][3]));
            }
            mt0 = fmaxf(mt0, __shfl_xor_sync(0xffffffffu, mt0, 1));
            mt0 = fmaxf(mt0, __shfl_xor_sync(0xffffffffu, mt0, 2));
            mt1 = fmaxf(mt1, __shfl_xor_sync(0xffffffffu, mt1, 1));
            mt1 = fmaxf(mt1, __shfl_xor_sync(0xffffffffu, mt1, 2));

            const float mn0 = fmaxf(mv0[mi], mt0), mn1 = fmaxf(mv1[mi], mt1);
            const float a0 = exp2f(mv0[mi] - mn0), a1 = exp2f(mv1[mi] - mn1);
            mv0[mi] = mn0; mv1[mi] = mn1;
            lv0[mi] *= a0; lv1[mi] *= a1;
#pragma unroll
            for (int ni = 0; ni < 8; ni++) {
                o[mi][ni][0] *= a0; o[mi][ni][1] *= a0;
                o[mi][ni][2] *= a1; o[mi][ni][3] *= a1;
            }

            float s0 = 0.0f, s1 = 0.0f;
#pragma unroll
            for (int ni = 0; ni < 8; ni++) {
                const float p0 = exp2f(scf[ni][0] - mn0);
                const float p1 = exp2f(scf[ni][1] - mn0);
                const float p2 = exp2f(scf[ni][2] - mn1);
                const float p3 = exp2f(scf[ni][3] - mn1);
                s0 += p0 + p1; s1 += p2 + p3;
                __half2 h0 = __floats2half2_rn(p0, p1);
                __half2 h1 = __floats2half2_rn(p2, p3);
                ph[mi][ni][0] = *(unsigned*)&h0;
                ph[mi][ni][1] = *(unsigned*)&h1;
            }
            s0 += __shfl_xor_sync(0xffffffffu, s0, 1);
            s0 += __shfl_xor_sync(0xffffffffu, s0, 2);
            s1 += __shfl_xor_sync(0xffffffffu, s1, 1);
            s1 += __shfl_xor_sync(0xffffffffu, s1, 2);
            lv0[mi] += s0; lv1[mi] += s1;
        }

        // O += P V : V B-frags shared across both mi groups (f32 acc)
#pragma unroll
        for (int ks = 0; ks < 4; ks++) {
#pragma unroll
            for (int ntp = 0; ntp < 4; ntp++) {
                unsigned r0, r1, r2, r3;
                const unsigned addr = sV + stg * ABUF +
                    ((ks * 16 + rvb) * AST + ntp * 16 + kvb) * 2;
                ldsm4t(r0, r1, r2, r3, addr);
                unsigned b0[2] = {r0, r1}, b1[2] = {r2, r3};
#pragma unroll
                for (int mi = 0; mi < 2; mi++) {
                    unsigned pa[4];
                    pa[0] = ph[mi][2 * ks][0];
                    pa[1] = ph[mi][2 * ks][1];
                    pa[2] = ph[mi][2 * ks + 1][0];
                    pa[3] = ph[mi][2 * ks + 1][1];
                    mma16816(o[mi][2 * ntp],     pa, b0);
                    mma16816(o[mi][2 * ntp + 1], pa, b1);
                }
            }
        }
    }

    // epilogue: normalize, write fp16 to g_attnh [B*S][D]
    const int b = bh >> 4, h = bh & (H_ - 1);
#pragma unroll
    for (int mi = 0; mi < 2; mi++) {
        const float i0 = 1.0f / lv0[mi], i1 = 1.0f / lv1[mi];
        __half* O0 = g_attnh + (size_t)(b * S_ + q0 + wq + mi * 16 + g) * D_ + h * HD_;
        __half* O1 = g_attnh + (size_t)(b * S_ + q0 + wq + mi * 16 + g + 8) * D_ + h * HD_;
#pragma unroll
        for (int ni = 0; ni < 8; ni++) {
            const int c = ni * 8 + 2 * tg;
            *(__half2*)(O0 + c) = __floats2half2_rn(o[mi][ni][0] * i0, o[mi][ni][1] * i0);
            *(__half2*)(O1 + c) = __floats2half2_rn(o[mi][ni][2] * i1, o[mi][ni][3] * i1);
        }
    }
}

// ---------------------------------------------------------------------------
extern "C" void kernel_launch(void* const* d_in, const int* in_sizes, int n_in,
                              void* d_out, int out_size)
{
    const float* x      = (const float*)d_in[0];
    const float* w_qkv  = (const float*)d_in[1];
    const float* b_qkv  = (const float*)d_in[2];
    const float* w_proj = (const float*)d_in[3];
    const float* b_proj = (const float*)d_in[4];
    float* out = (float*)d_out;

    __half *xh, *wqkvh, *wprojh;
    cudaGetSymbolAddress((void**)&xh,     g_xh);
    cudaGetSymbolAddress((void**)&wqkvh,  g_wqkvh);
    cudaGetSymbolAddress((void**)&wprojh, g_wprojh);

    cudaFuncSetAttribute((const void*)gemm_h<1, 128, 2, 3>,
                         cudaFuncAttributeMaxDynamicSharedMemorySize, GSMEM(128, 2));
    cudaFuncSetAttribute((const void*)gemm_h<0, 64, 2, 4>,
                         cudaFuncAttributeMaxDynamicSharedMemorySize, GSMEM(64, 2));
    cudaFuncSetAttribute((const void*)attn_h,
                         cudaFuncAttributeMaxDynamicSharedMemorySize, ASMEM);

    // 0) fp32 -> fp16 (single launch)
    cvt_all<<<(N1_ + N2_ + N3_) / 4 / 256, 256>>>(x, w_qkv, w_proj);

    // 1) QKV projection -> g_qkvh [3,B,H,S,hd] (fp16): 2-stage, 3 CTAs/SM
    dim3 g1((3 * D_) / 128, M_ / 128);   // (24, 32)
    gemm_h<1, 128, 2, 3><<<g1, 128, GSMEM(128, 2)>>>(xh, wqkvh, b_qkv, nullptr, 3 * D_, D_);

    // 2) attention -> g_attnh [B,S,D] (fp16): fp16 QK acc, 3 CTAs/SM
    attn_h<<<dim3(S_ / 128, B_ * H_), 128, ASMEM>>>();

    // 3) output projection -> d_out (fp32): BM=64, 2-stage, 4 CTAs/SM
    dim3 g2(D_ / 128, M_ / 64);          // (8, 64)
    gemm_h<0, 64, 2, 4><<<g2, 128, GSMEM(64, 2)>>>(nullptr, wprojh, b_proj, out, D_, D_);
}

// round 15
// speedup vs baseline: 1.0806x; 1.0806x over previous
#include <cuda_runtime.h>
#include <cuda_fp16.h>
#include <cstdint>

// Problem constants
#define B_  2
#define S_  2048
#define D_  1024
#define H_  16
#define HD_ 64
#define M_  (B_ * S_)   // 4096

// Scratch (allocation-free rule: __device__ globals)
__device__ __half g_xh[(size_t)M_ * D_];
__device__ __half g_wqkvh[(size_t)3 * D_ * D_];
__device__ __half g_wprojh[(size_t)D_ * D_];
__device__ __half g_qkvh[(size_t)3 * B_ * H_ * S_ * HD_];  // [3][B][H][S][hd]
__device__ __half g_attnh[(size_t)M_ * D_];

// ---------------------------------------------------------------------------
// helpers
// ---------------------------------------------------------------------------
__device__ __forceinline__ unsigned smem_u32(const void* p) {
    return (unsigned)__cvta_generic_to_shared(p);
}
__device__ __forceinline__ void cp_async16(unsigned dst, const void* src) {
    asm volatile("cp.async.cg.shared.global [%0], [%1], 16;\n" :: "r"(dst), "l"(src));
}
__device__ __forceinline__ void cp_commit() {
    asm volatile("cp.async.commit_group;\n");
}
template<int N>
__device__ __forceinline__ void cp_wait() {
    asm volatile("cp.async.wait_group %0;\n" :: "n"(N));
}
__device__ __forceinline__ void ldsm4(unsigned& r0, unsigned& r1, unsigned& r2,
                                      unsigned& r3, unsigned a) {
    asm volatile("ldmatrix.sync.aligned.m8n8.x4.shared.b16 {%0,%1,%2,%3},[%4];"
                 : "=r"(r0), "=r"(r1), "=r"(r2), "=r"(r3) : "r"(a));
}
__device__ __forceinline__ void ldsm4t(unsigned& r0, unsigned& r1, unsigned& r2,
                                       unsigned& r3, unsigned a) {
    asm volatile("ldmatrix.sync.aligned.m8n8.x4.trans.shared.b16 {%0,%1,%2,%3},[%4];"
                 : "=r"(r0), "=r"(r1), "=r"(r2), "=r"(r3) : "r"(a));
}
__device__ __forceinline__ void mma16816(float* c, const unsigned* a, const unsigned* b) {
    asm volatile("mma.sync.aligned.m16n8k16.row.col.f32.f16.f16.f32 "
                 "{%0,%1,%2,%3},{%4,%5,%6,%7},{%8,%9},{%0,%1,%2,%3};"
                 : "+f"(c[0]), "+f"(c[1]), "+f"(c[2]), "+f"(c[3])
                 : "r"(a[0]), "r"(a[1]), "r"(a[2]), "r"(a[3]), "r"(b[0]), "r"(b[1]));
}

// ---------------------------------------------------------------------------
// fp32 -> fp16 convert: one launch for all three tensors
// ---------------------------------------------------------------------------
#define N1_ (M_ * D_)          // x
#define N2_ (3 * D_ * D_)      // w_qkv
#define N3_ (D_ * D_)          // w_proj

__global__ void cvt_all(const float* __restrict__ x,
                        const float* __restrict__ wq,
                        const float* __restrict__ wp) {
    const int i = (blockIdx.x * blockDim.x + threadIdx.x) * 4;
    const float* src;
    __half* dst;
    int off;
    if (i < N1_)            { src = x;  dst = g_xh;     off = i; }
    else if (i < N1_ + N2_) { src = wq; dst = g_wqkvh;  off = i - N1_; }
    else                    { src = wp; dst = g_wprojh; off = i - N1_ - N2_; }
    float4 v = *(const float4*)(src + off);
    *(__half2*)(dst + off)     = __floats2half2_rn(v.x, v.y);
    *(__half2*)(dst + off + 2) = __floats2half2_rn(v.z, v.w);
}

// ---------------------------------------------------------------------------
// fp16 mma.sync GEMM (round-12 best, unchanged): BK=64, 2-stage ring,
// 128 threads (4 warps 2x2).
// gemm1: BM=128, 3 CTAs/SM. proj: BM=64, 4 CTAs/SM.
// ---------------------------------------------------------------------------
#define GST 72                           // smem row stride in halves (64 + 8)
#define GABUF(BM_) ((BM_) * GST * 2)     // A bytes per stage
#define GBBUF (128 * GST * 2)            // B bytes per stage
#define GSMEM(BM_, ST_) ((ST_) * (GABUF(BM_) + GBBUF))

template<int SCATTER, int BM_, int STAGES_, int MINB_>
__global__ __launch_bounds__(128, MINB_)
void gemm_h(const __half* __restrict__ Ain, const __half* __restrict__ W,
            const float* __restrict__ bias, float* __restrict__ C,
            int N, int K)
{
    extern __shared__ char dsm[];
    const __half* A = Ain ? Ain : g_attnh;
    constexpr int MI = BM_ / 32;         // m16 groups per warp (4 or 2)
    constexpr int PF = STAGES_ - 1;      // prefetch distance

    const int tid = threadIdx.x;
    const int lane = tid & 31, warp = tid >> 5;
    const int wm = warp & 1, wn = warp >> 1;
    const int g = lane >> 2, tg = lane & 3;
    const int m0 = blockIdx.y * BM_, n0 = blockIdx.x * 128;

    const unsigned sA = smem_u32(dsm);
    const unsigned sB = sA + STAGES_ * GABUF(BM_);

    const int ra = (lane & 7) + 8 * ((lane >> 3) & 1);
    const int ka = 8 * (lane >> 4);
    const int rb = (lane & 7) + 8 * (lane >> 4);
    const int kb = 8 * ((lane >> 3) & 1);

    float acc[MI][8][4];
#pragma unroll
    for (int mi = 0; mi < MI; mi++)
#pragma unroll
        for (int ni = 0; ni < 8; ni++)
#pragma unroll
            for (int c = 0; c < 4; c++) acc[mi][ni][c] = 0.0f;

    const __half* aA = A + (size_t)m0 * K;
    const __half* aW = W + (size_t)n0 * K;

    auto prefetch = [&](int it) {
        const int stg = it % STAGES_;
        const int k0 = it * 64;
#pragma unroll
        for (int i = 0; i < BM_ / 16; i++) {     // A: BM_ rows x 8 chunks
            const int c = tid + i * 128;
            const int row = c >> 3, q = c & 7;
            cp_async16(sA + stg * GABUF(BM_) + (row * GST + q * 8) * 2,
                       aA + (size_t)row * K + k0 + q * 8);
        }
#pragma unroll
        for (int i = 0; i < 8; i++) {            // B: 128 rows x 8 chunks
            const int c = tid + i * 128;
            const int row = c >> 3, q = c & 7;
            cp_async16(sB + stg * GBBUF + (row * GST + q * 8) * 2,
                       aW + (size_t)row * K + k0 + q * 8);
        }
        cp_commit();
    };

    const int T = K / 64;                // 16
#pragma unroll
    for (int i = 0; i < PF; i++) prefetch(i);

    for (int it = 0; it < T; it++) {
        cp_wait<PF - 1>();
        __syncthreads();
        if (it + PF < T) prefetch(it + PF); else cp_commit();

        const int stg = it % STAGES_;
#pragma unroll
        for (int ks = 0; ks < 4; ks++) {
            unsigned af[MI][4];
#pragma unroll
            for (int mi = 0; mi < MI; mi++) {
                const unsigned addr = sA + stg * GABUF(BM_) +
                    ((wm * (BM_ / 2) + mi * 16 + ra) * GST + ks * 16 + ka) * 2;
                ldsm4(af[mi][0], af[mi][1], af[mi][2], af[mi][3], addr);
            }
            unsigned bf[8][2];
#pragma unroll
            for (int ntp = 0; ntp < 4; ntp++) {
                unsigned r0, r1, r2, r3;
                const unsigned addr = sB + stg * GBBUF +
                    ((wn * 64 + ntp * 16 + rb) * GST + ks * 16 + kb) * 2;
                ldsm4(r0, r1, r2, r3, addr);
                bf[2 * ntp][0] = r0; bf[2 * ntp][1] = r1;
                bf[2 * ntp + 1][0] = r2; bf[2 * ntp + 1][1] = r3;
            }
#pragma unroll
            for (int mi = 0; mi < MI; mi++)
#pragma unroll
                for (int ni = 0; ni < 8; ni++)
                    mma16816(acc[mi][ni], af[mi], bf[ni]);
        }
    }

#pragma unroll
    for (int mi = 0; mi < MI; mi++) {
#pragma unroll
        for (int half = 0; half < 2; half++) {
            const int m = m0 + wm * (BM_ / 2) + mi * 16 + g + half * 8;
#pragma unroll
            for (int ni = 0; ni < 8; ni++) {
                const int n = n0 + wn * 64 + ni * 8 + 2 * tg;
                const float v0 = acc[mi][ni][half * 2 + 0] + bias[n];
                const float v1 = acc[mi][ni][half * 2 + 1] + bias[n + 1];
                if (SCATTER) {
                    const int three = n >> 10;
                    const int h = (n >> 6) & (H_ - 1);
                    const int d = n & (HD_ - 1);
                    const int b = m >> 11;
                    const int s = m & (S_ - 1);
                    *(__half2*)&g_qkvh[((size_t)three * (B_ * H_) + b * H_ + h) * (S_ * HD_)
                                       + (size_t)s * HD_ + d] = __floats2half2_rn(v0, v1);
                } else {
                    *(float2*)&C[(size_t)m * N + n] = make_float2(v0, v1);
                }
            }
        }
    }
}

// ---------------------------------------------------------------------------
// fp16 mma.sync flash attention (round-12 structure: m32 warp tiles, f32 QK
// acc, 2 CTAs/SM) with half2-MUFU softmax: exp evaluated via h2exp2 on
// packed (s - m) pairs -> MUFU count halved; sums via __hadd2 tree (fma pipe).
// CTA = 128 queries x 1 (b,h); 4 warps x 32 q. 64-key tiles, 3-stage ring.
// grid = (S/128, B*H), block = 128.
// ---------------------------------------------------------------------------
#define AST 72
#define ABUF (64 * AST * 2)
#define ASTAGES 3
#define ASMEM (2 * ASTAGES * ABUF)
#define SCALE_LOG2E 0.1803368801111244f   // 0.125 * log2(e)

__global__ __launch_bounds__(128)
void attn_h()
{
    extern __shared__ char dsm[];
    const int bh = blockIdx.y;
    const int q0 = blockIdx.x * 128;
    const int tid = threadIdx.x;
    const int warp = tid >> 5, lane = tid & 31;
    const int g = lane >> 2, tg = lane & 3;
    const int wq = warp * 32;

    const __half* Qp = g_qkvh + (size_t)bh * (S_ * HD_);
    const __half* Kp = g_qkvh + (size_t)(B_ * H_ + bh) * (S_ * HD_);
    const __half* Vp = g_qkvh + (size_t)(2 * B_ * H_ + bh) * (S_ * HD_);

    const unsigned sK = smem_u32(dsm);
    const unsigned sV = sK + ASTAGES * ABUF;

    unsigned qa[2][4][4];
#pragma unroll
    for (int mi = 0; mi < 2; mi++) {
        const __half* Qr0 = Qp + (size_t)(q0 + wq + mi * 16 + g) * HD_;
        const __half* Qr1 = Qp + (size_t)(q0 + wq + mi * 16 + g + 8) * HD_;
#pragma unroll
        for (int ks = 0; ks < 4; ks++) {
            qa[mi][ks][0] = *(const unsigned*)(Qr0 + ks * 16 + 2 * tg);
            qa[mi][ks][1] = *(const unsigned*)(Qr1 + ks * 16 + 2 * tg);
            qa[mi][ks][2] = *(const unsigned*)(Qr0 + ks * 16 + 8 + 2 * tg);
            qa[mi][ks][3] = *(const unsigned*)(Qr1 + ks * 16 + 8 + 2 * tg);
        }
    }

    const int rkb = (lane & 7) + 8 * (lane >> 4);
    const int kkb = 8 * ((lane >> 3) & 1);
    const int rvb = (lane & 7) + 8 * ((lane >> 3) & 1);
    const int kvb = 8 * (lane >> 4);

    float o[2][8][4];
#pragma unroll
    for (int mi = 0; mi < 2; mi++)
#pragma unroll
        for (int ni = 0; ni < 8; ni++)
#pragma unroll
            for (int c = 0; c < 4; c++) o[mi][ni][c] = 0.0f;
    float mv0[2] = {-3.0e38f, -3.0e38f}, mv1[2] = {-3.0e38f, -3.0e38f};
    float lv0[2] = {0.0f, 0.0f},         lv1[2] = {0.0f, 0.0f};

    auto prefetch = [&](int it) {
        const int stg = it % ASTAGES;
        const int kt = it * 64;
#pragma unroll
        for (int i = 0; i < 4; i++) {
            const int c = tid + i * 128;
            const int row = c >> 3, q = c & 7;
            cp_async16(sK + stg * ABUF + (row * AST + q * 8) * 2,
                       Kp + (size_t)(kt + row) * HD_ + q * 8);
            cp_async16(sV + stg * ABUF + (row * AST + q * 8) * 2,
                       Vp + (size_t)(kt + row) * HD_ + q * 8);
        }
        cp_commit();
    };

    const int T = S_ / 64;   // 32
    prefetch(0); prefetch(1);

    for (int it = 0; it < T; it++) {
        cp_wait<1>();
        __syncthreads();
        if (it + 2 < T) prefetch(it + 2); else cp_commit();

        const int stg = it % ASTAGES;

        // S = Q K^T (f32 acc, round-12 proven layout)
        float sc[2][8][4];
#pragma unroll
        for (int mi = 0; mi < 2; mi++)
#pragma unroll
            for (int ni = 0; ni < 8; ni++)
#pragma unroll
                for (int c = 0; c < 4; c++) sc[mi][ni][c] = 0.0f;
#pragma unroll
        for (int ks = 0; ks < 4; ks++) {
#pragma unroll
            for (int ntp = 0; ntp < 4; ntp++) {
                unsigned r0, r1, r2, r3;
                const unsigned addr = sK + stg * ABUF +
                    ((ntp * 16 + rkb) * AST + ks * 16 + kkb) * 2;
                ldsm4(r0, r1, r2, r3, addr);
                unsigned b0[2] = {r0, r1}, b1[2] = {r2, r3};
#pragma unroll
                for (int mi = 0; mi < 2; mi++) {
                    mma16816(sc[mi][2 * ntp],     qa[mi][ks], b0);
                    mma16816(sc[mi][2 * ntp + 1], qa[mi][ks], b1);
                }
            }
        }
#pragma unroll
        for (int mi = 0; mi < 2; mi++)
#pragma unroll
            for (int ni = 0; ni < 8; ni++)
#pragma unroll
                for (int c = 0; c < 4; c++) sc[mi][ni][c] *= SCALE_LOG2E;

        // online softmax with half2 exp (h2exp2 -> half the MUFU ops)
        unsigned ph[2][8][2];
#pragma unroll
        for (int mi = 0; mi < 2; mi++) {
            float mt0 = -3.0e38f, mt1 = -3.0e38f;
#pragma unroll
            for (int ni = 0; ni < 8; ni++) {
                mt0 = fmaxf(mt0, fmaxf(sc[mi][ni][0], sc[mi][ni][1]));
                mt1 = fmaxf(mt1, fmaxf(sc[mi][ni][2], sc[mi][ni][3]));
            }
            mt0 = fmaxf(mt0, __shfl_xor_sync(0xffffffffu, mt0, 1));
            mt0 = fmaxf(mt0, __shfl_xor_sync(0xffffffffu, mt0, 2));
            mt1 = fmaxf(mt1, __shfl_xor_sync(0xffffffffu, mt1, 1));
            mt1 = fmaxf(mt1, __shfl_xor_sync(0xffffffffu, mt1, 2));

            const float mn0 = fmaxf(mv0[mi], mt0), mn1 = fmaxf(mv1[mi], mt1);
            const float a0 = exp2f(mv0[mi] - mn0), a1 = exp2f(mv1[mi] - mn1);
            mv0[mi] = mn0; mv1[mi] = mn1;
            lv0[mi] *= a0; lv1[mi] *= a1;
#pragma unroll
            for (int ni = 0; ni < 8; ni++) {
                o[mi][ni][0] *= a0; o[mi][ni][1] *= a0;
                o[mi][ni][2] *= a1; o[mi][ni][3] *= a1;
            }

            __half2 sum0 = __float2half2_rn(0.0f);
            __half2 sum1 = __float2half2_rn(0.0f);
#pragma unroll
            for (int ni = 0; ni < 8; ni++) {
                // pack (s - m) pairs to fp16, single f16x2 MUFU per pair
                __half2 d0 = __floats2half2_rn(sc[mi][ni][0] - mn0,
                                               sc[mi][ni][1] - mn0);
                __half2 d1 = __floats2half2_rn(sc[mi][ni][2] - mn1,
                                               sc[mi][ni][3] - mn1);
                __half2 p0 = h2exp2(d0);
                __half2 p1 = h2exp2(d1);
                ph[mi][ni][0] = *(unsigned*)&p0;   // exp output IS the P frag
                ph[mi][ni][1] = *(unsigned*)&p1;
                sum0 = __hadd2(sum0, p0);
                sum1 = __hadd2(sum1, p1);
            }
            float2 f0 = __half22float2(sum0);
            float2 f1 = __half22float2(sum1);
            float s0 = f0.x + f0.y, s1 = f1.x + f1.y;
            s0 += __shfl_xor_sync(0xffffffffu, s0, 1);
            s0 += __shfl_xor_sync(0xffffffffu, s0, 2);
            s1 += __shfl_xor_sync(0xffffffffu, s1, 1);
            s1 += __shfl_xor_sync(0xffffffffu, s1, 2);
            lv0[mi] += s0; lv1[mi] += s1;
        }

        // O += P V : V B-frags shared across both mi groups (f32 acc)
#pragma unroll
        for (int ks = 0; ks < 4; ks++) {
#pragma unroll
            for (int ntp = 0; ntp < 4; ntp++) {
                unsigned r0, r1, r2, r3;
                const unsigned addr = sV + stg * ABUF +
                    ((ks * 16 + rvb) * AST + ntp * 16 + kvb) * 2;
                ldsm4t(r0, r1, r2, r3, addr);
                unsigned b0[2] = {r0, r1}, b1[2] = {r2, r3};
#pragma unroll
                for (int mi = 0; mi < 2; mi++) {
                    unsigned pa[4];
                    pa[0] = ph[mi][2 * ks][0];
                    pa[1] = ph[mi][2 * ks][1];
                    pa[2] = ph[mi][2 * ks + 1][0];
                    pa[3] = ph[mi][2 * ks + 1][1];
                    mma16816(o[mi][2 * ntp],     pa, b0);
                    mma16816(o[mi][2 * ntp + 1], pa, b1);
                }
            }
        }
    }

    // epilogue: normalize, write fp16 to g_attnh [B*S][D]
    const int b = bh >> 4, h = bh & (H_ - 1);
#pragma unroll
    for (int mi = 0; mi < 2; mi++) {
        const float i0 = 1.0f / lv0[mi], i1 = 1.0f / lv1[mi];
        __half* O0 = g_attnh + (size_t)(b * S_ + q0 + wq + mi * 16 + g) * D_ + h * HD_;
        __half* O1 = g_attnh + (size_t)(b * S_ + q0 + wq + mi * 16 + g + 8) * D_ + h * HD_;
#pragma unroll
        for (int ni = 0; ni < 8; ni++) {
            const int c = ni * 8 + 2 * tg;
            *(__half2*)(O0 + c) = __floats2half2_rn(o[mi][ni][0] * i0, o[mi][ni][1] * i0);
            *(__half2*)(O1 + c) = __floats2half2_rn(o[mi][ni][2] * i1, o[mi][ni][3] * i1);
        }
    }
}

// ---------------------------------------------------------------------------
extern "C" void kernel_launch(void* const* d_in, const int* in_sizes, int n_in,
                              void* d_out, int out_size)
{
    const float* x      = (const float*)d_in[0];
    const float* w_qkv  = (const float*)d_in[1];
    const float* b_qkv  = (const float*)d_in[2];
    const float* w_proj = (const float*)d_in[3];
    const float* b_proj = (const float*)d_in[4];
    float* out = (float*)d_out;

    __half *xh, *wqkvh, *wprojh;
    cudaGetSymbolAddress((void**)&xh,     g_xh);
    cudaGetSymbolAddress((void**)&wqkvh,  g_wqkvh);
    cudaGetSymbolAddress((void**)&wprojh, g_wprojh);

    cudaFuncSetAttribute((const void*)gemm_h<1, 128, 2, 3>,
                         cudaFuncAttributeMaxDynamicSharedMemorySize, GSMEM(128, 2));
    cudaFuncSetAttribute((const void*)gemm_h<0, 64, 2, 4>,
                         cudaFuncAttributeMaxDynamicSharedMemorySize, GSMEM(64, 2));
    cudaFuncSetAttribute((const void*)attn_h,
                         cudaFuncAttributeMaxDynamicSharedMemorySize, ASMEM);

    // 0) fp32 -> fp16 (single launch)
    cvt_all<<<(N1_ + N2_ + N3_) / 4 / 256, 256>>>(x, w_qkv, w_proj);

    // 1) QKV projection -> g_qkvh [3,B,H,S,hd] (fp16): 2-stage, 3 CTAs/SM
    dim3 g1((3 * D_) / 128, M_ / 128);   // (24, 32)
    gemm_h<1, 128, 2, 3><<<g1, 128, GSMEM(128, 2)>>>(xh, wqkvh, b_qkv, nullptr, 3 * D_, D_);

    // 2) attention -> g_attnh [B,S,D] (fp16): half2-MUFU softmax
    attn_h<<<dim3(S_ / 128, B_ * H_), 128, ASMEM>>>();

    // 3) output projection -> d_out (fp32): BM=64, 2-stage, 4 CTAs/SM
    dim3 g2(D_ / 128, M_ / 64);          // (8, 64)
    gemm_h<0, 64, 2, 4><<<g2, 128, GSMEM(64, 2)>>>(nullptr, wprojh, b_proj, out, D_, D_);
}

// round 16
// speedup vs baseline: 1.1136x; 1.0305x over previous
#include <cuda_runtime.h>
#include <cuda_fp16.h>
#include <cstdint>

// Problem constants
#define B_  2
#define S_  2048
#define D_  1024
#define H_  16
#define HD_ 64
#define M_  (B_ * S_)   // 4096

// Scratch (allocation-free rule: __device__ globals)
__device__ __half g_xh[(size_t)M_ * D_];
__device__ __half g_wqkvh[(size_t)3 * D_ * D_];
__device__ __half g_wprojh[(size_t)D_ * D_];
__device__ __half g_qkvh[(size_t)3 * B_ * H_ * S_ * HD_];  // [3][B][H][S][hd]
__device__ __half g_attnh[(size_t)M_ * D_];

// ---------------------------------------------------------------------------
// helpers
// ---------------------------------------------------------------------------
__device__ __forceinline__ unsigned smem_u32(const void* p) {
    return (unsigned)__cvta_generic_to_shared(p);
}
__device__ __forceinline__ void cp_async16(unsigned dst, const void* src) {
    asm volatile("cp.async.cg.shared.global [%0], [%1], 16;\n" :: "r"(dst), "l"(src));
}
__device__ __forceinline__ void cp_commit() {
    asm volatile("cp.async.commit_group;\n");
}
template<int N>
__device__ __forceinline__ void cp_wait() {
    asm volatile("cp.async.wait_group %0;\n" :: "n"(N));
}
__device__ __forceinline__ void ldsm4(unsigned& r0, unsigned& r1, unsigned& r2,
                                      unsigned& r3, unsigned a) {
    asm volatile("ldmatrix.sync.aligned.m8n8.x4.shared.b16 {%0,%1,%2,%3},[%4];"
                 : "=r"(r0), "=r"(r1), "=r"(r2), "=r"(r3) : "r"(a));
}
__device__ __forceinline__ void ldsm4t(unsigned& r0, unsigned& r1, unsigned& r2,
                                       unsigned& r3, unsigned a) {
    asm volatile("ldmatrix.sync.aligned.m8n8.x4.trans.shared.b16 {%0,%1,%2,%3},[%4];"
                 : "=r"(r0), "=r"(r1), "=r"(r2), "=r"(r3) : "r"(a));
}
__device__ __forceinline__ void mma16816(float* c, const unsigned* a, const unsigned* b) {
    asm volatile("mma.sync.aligned.m16n8k16.row.col.f32.f16.f16.f32 "
                 "{%0,%1,%2,%3},{%4,%5,%6,%7},{%8,%9},{%0,%1,%2,%3};"
                 : "+f"(c[0]), "+f"(c[1]), "+f"(c[2]), "+f"(c[3])
                 : "r"(a[0]), "r"(a[1]), "r"(a[2]), "r"(a[3]), "r"(b[0]), "r"(b[1]));
}

// ---------------------------------------------------------------------------
// fp32 -> fp16 convert: one launch for all three tensors
// ---------------------------------------------------------------------------
#define N1_ (M_ * D_)          // x
#define N2_ (3 * D_ * D_)      // w_qkv
#define N3_ (D_ * D_)          // w_proj

__global__ void cvt_all(const float* __restrict__ x,
                        const float* __restrict__ wq,
                        const float* __restrict__ wp) {
    const int i = (blockIdx.x * blockDim.x + threadIdx.x) * 4;
    const float* src;
    __half* dst;
    int off;
    if (i < N1_)            { src = x;  dst = g_xh;     off = i; }
    else if (i < N1_ + N2_) { src = wq; dst = g_wqkvh;  off = i - N1_; }
    else                    { src = wp; dst = g_wprojh; off = i - N1_ - N2_; }
    float4 v = *(const float4*)(src + off);
    *(__half2*)(dst + off)     = __floats2half2_rn(v.x, v.y);
    *(__half2*)(dst + off + 2) = __floats2half2_rn(v.z, v.w);
}

// ---------------------------------------------------------------------------
// fp16 mma.sync GEMM (round-12 best, unchanged): BK=64, 2-stage ring,
// 128 threads (4 warps 2x2).
// gemm1: BM=128, 3 CTAs/SM. proj: BM=64, 4 CTAs/SM.
// ---------------------------------------------------------------------------
#define GST 72                           // smem row stride in halves (64 + 8)
#define GABUF(BM_) ((BM_) * GST * 2)     // A bytes per stage
#define GBBUF (128 * GST * 2)            // B bytes per stage
#define GSMEM(BM_, ST_) ((ST_) * (GABUF(BM_) + GBBUF))

template<int SCATTER, int BM_, int STAGES_, int MINB_>
__global__ __launch_bounds__(128, MINB_)
void gemm_h(const __half* __restrict__ Ain, const __half* __restrict__ W,
            const float* __restrict__ bias, float* __restrict__ C,
            int N, int K)
{
    extern __shared__ char dsm[];
    const __half* A = Ain ? Ain : g_attnh;
    constexpr int MI = BM_ / 32;         // m16 groups per warp (4 or 2)
    constexpr int PF = STAGES_ - 1;      // prefetch distance

    const int tid = threadIdx.x;
    const int lane = tid & 31, warp = tid >> 5;
    const int wm = warp & 1, wn = warp >> 1;
    const int g = lane >> 2, tg = lane & 3;
    const int m0 = blockIdx.y * BM_, n0 = blockIdx.x * 128;

    const unsigned sA = smem_u32(dsm);
    const unsigned sB = sA + STAGES_ * GABUF(BM_);

    const int ra = (lane & 7) + 8 * ((lane >> 3) & 1);
    const int ka = 8 * (lane >> 4);
    const int rb = (lane & 7) + 8 * (lane >> 4);
    const int kb = 8 * ((lane >> 3) & 1);

    float acc[MI][8][4];
#pragma unroll
    for (int mi = 0; mi < MI; mi++)
#pragma unroll
        for (int ni = 0; ni < 8; ni++)
#pragma unroll
            for (int c = 0; c < 4; c++) acc[mi][ni][c] = 0.0f;

    const __half* aA = A + (size_t)m0 * K;
    const __half* aW = W + (size_t)n0 * K;

    auto prefetch = [&](int it) {
        const int stg = it % STAGES_;
        const int k0 = it * 64;
#pragma unroll
        for (int i = 0; i < BM_ / 16; i++) {     // A: BM_ rows x 8 chunks
            const int c = tid + i * 128;
            const int row = c >> 3, q = c & 7;
            cp_async16(sA + stg * GABUF(BM_) + (row * GST + q * 8) * 2,
                       aA + (size_t)row * K + k0 + q * 8);
        }
#pragma unroll
        for (int i = 0; i < 8; i++) {            // B: 128 rows x 8 chunks
            const int c = tid + i * 128;
            const int row = c >> 3, q = c & 7;
            cp_async16(sB + stg * GBBUF + (row * GST + q * 8) * 2,
                       aW + (size_t)row * K + k0 + q * 8);
        }
        cp_commit();
    };

    const int T = K / 64;                // 16
#pragma unroll
    for (int i = 0; i < PF; i++) prefetch(i);

    for (int it = 0; it < T; it++) {
        cp_wait<PF - 1>();
        __syncthreads();
        if (it + PF < T) prefetch(it + PF); else cp_commit();

        const int stg = it % STAGES_;
#pragma unroll
        for (int ks = 0; ks < 4; ks++) {
            unsigned af[MI][4];
#pragma unroll
            for (int mi = 0; mi < MI; mi++) {
                const unsigned addr = sA + stg * GABUF(BM_) +
                    ((wm * (BM_ / 2) + mi * 16 + ra) * GST + ks * 16 + ka) * 2;
                ldsm4(af[mi][0], af[mi][1], af[mi][2], af[mi][3], addr);
            }
            unsigned bf[8][2];
#pragma unroll
            for (int ntp = 0; ntp < 4; ntp++) {
                unsigned r0, r1, r2, r3;
                const unsigned addr = sB + stg * GBBUF +
                    ((wn * 64 + ntp * 16 + rb) * GST + ks * 16 + kb) * 2;
                ldsm4(r0, r1, r2, r3, addr);
                bf[2 * ntp][0] = r0; bf[2 * ntp][1] = r1;
                bf[2 * ntp + 1][0] = r2; bf[2 * ntp + 1][1] = r3;
            }
#pragma unroll
            for (int mi = 0; mi < MI; mi++)
#pragma unroll
                for (int ni = 0; ni < 8; ni++)
                    mma16816(acc[mi][ni], af[mi], bf[ni]);
        }
    }

#pragma unroll
    for (int mi = 0; mi < MI; mi++) {
#pragma unroll
        for (int half = 0; half < 2; half++) {
            const int m = m0 + wm * (BM_ / 2) + mi * 16 + g + half * 8;
#pragma unroll
            for (int ni = 0; ni < 8; ni++) {
                const int n = n0 + wn * 64 + ni * 8 + 2 * tg;
                const float v0 = acc[mi][ni][half * 2 + 0] + bias[n];
                const float v1 = acc[mi][ni][half * 2 + 1] + bias[n + 1];
                if (SCATTER) {
                    const int three = n >> 10;
                    const int h = (n >> 6) & (H_ - 1);
                    const int d = n & (HD_ - 1);
                    const int b = m >> 11;
                    const int s = m & (S_ - 1);
                    *(__half2*)&g_qkvh[((size_t)three * (B_ * H_) + b * H_ + h) * (S_ * HD_)
                                       + (size_t)s * HD_ + d] = __floats2half2_rn(v0, v1);
                } else {
                    *(float2*)&C[(size_t)m * N + n] = make_float2(v0, v1);
                }
            }
        }
    }
}

// ---------------------------------------------------------------------------
// fp16 mma.sync flash attention (round-12 best structure: m32 warp tiles,
// f32 QK acc, 64-key tiles, 3-stage ring) with the softmax scale folded
// into Q at load time (one-time __hmul2) — per-iter scale pass removed.
// CTA = 128 queries x 1 (b,h); 4 warps x 32 q. grid = (S/128, B*H), block=128.
// ---------------------------------------------------------------------------
#define AST 72
#define ABUF (64 * AST * 2)
#define ASTAGES 3
#define ASMEM (2 * ASTAGES * ABUF)
#define SCALE_LOG2E 0.1803368801111244f   // 0.125 * log2(e)

__global__ __launch_bounds__(128)
void attn_h()
{
    extern __shared__ char dsm[];
    const int bh = blockIdx.y;
    const int q0 = blockIdx.x * 128;
    const int tid = threadIdx.x;
    const int warp = tid >> 5, lane = tid & 31;
    const int g = lane >> 2, tg = lane & 3;
    const int wq = warp * 32;

    const __half* Qp = g_qkvh + (size_t)bh * (S_ * HD_);
    const __half* Kp = g_qkvh + (size_t)(B_ * H_ + bh) * (S_ * HD_);
    const __half* Vp = g_qkvh + (size_t)(2 * B_ * H_ + bh) * (S_ * HD_);

    const unsigned sK = smem_u32(dsm);
    const unsigned sV = sK + ASTAGES * ABUF;

    // Q fragments pre-scaled by 0.125*log2(e): S emerges in log2 domain
    const __half2 qscale = __float2half2_rn(SCALE_LOG2E);
    unsigned qa[2][4][4];
#pragma unroll
    for (int mi = 0; mi < 2; mi++) {
        const __half* Qr0 = Qp + (size_t)(q0 + wq + mi * 16 + g) * HD_;
        const __half* Qr1 = Qp + (size_t)(q0 + wq + mi * 16 + g + 8) * HD_;
#pragma unroll
        for (int ks = 0; ks < 4; ks++) {
            __half2 v0 = __hmul2(*(const __half2*)(Qr0 + ks * 16 + 2 * tg),     qscale);
            __half2 v1 = __hmul2(*(const __half2*)(Qr1 + ks * 16 + 2 * tg),     qscale);
            __half2 v2 = __hmul2(*(const __half2*)(Qr0 + ks * 16 + 8 + 2 * tg), qscale);
            __half2 v3 = __hmul2(*(const __half2*)(Qr1 + ks * 16 + 8 + 2 * tg), qscale);
            qa[mi][ks][0] = *(unsigned*)&v0;
            qa[mi][ks][1] = *(unsigned*)&v1;
            qa[mi][ks][2] = *(unsigned*)&v2;
            qa[mi][ks][3] = *(unsigned*)&v3;
        }
    }

    const int rkb = (lane & 7) + 8 * (lane >> 4);
    const int kkb = 8 * ((lane >> 3) & 1);
    const int rvb = (lane & 7) + 8 * ((lane >> 3) & 1);
    const int kvb = 8 * (lane >> 4);

    float o[2][8][4];
#pragma unroll
    for (int mi = 0; mi < 2; mi++)
#pragma unroll
        for (int ni = 0; ni < 8; ni++)
#pragma unroll
            for (int c = 0; c < 4; c++) o[mi][ni][c] = 0.0f;
    float mv0[2] = {-3.0e38f, -3.0e38f}, mv1[2] = {-3.0e38f, -3.0e38f};
    float lv0[2] = {0.0f, 0.0f},         lv1[2] = {0.0f, 0.0f};

    auto prefetch = [&](int it) {
        const int stg = it % ASTAGES;
        const int kt = it * 64;
#pragma unroll
        for (int i = 0; i < 4; i++) {
            const int c = tid + i * 128;
            const int row = c >> 3, q = c & 7;
            cp_async16(sK + stg * ABUF + (row * AST + q * 8) * 2,
                       Kp + (size_t)(kt + row) * HD_ + q * 8);
            cp_async16(sV + stg * ABUF + (row * AST + q * 8) * 2,
                       Vp + (size_t)(kt + row) * HD_ + q * 8);
        }
        cp_commit();
    };

    const int T = S_ / 64;   // 32
    prefetch(0); prefetch(1);

    for (int it = 0; it < T; it++) {
        cp_wait<1>();
        __syncthreads();
        if (it + 2 < T) prefetch(it + 2); else cp_commit();

        const int stg = it % ASTAGES;

        // S = Q' K^T : already scaled & in log2 domain
        float sc[2][8][4];
#pragma unroll
        for (int mi = 0; mi < 2; mi++)
#pragma unroll
            for (int ni = 0; ni < 8; ni++)
#pragma unroll
                for (int c = 0; c < 4; c++) sc[mi][ni][c] = 0.0f;
#pragma unroll
        for (int ks = 0; ks < 4; ks++) {
#pragma unroll
            for (int ntp = 0; ntp < 4; ntp++) {
                unsigned r0, r1, r2, r3;
                const unsigned addr = sK + stg * ABUF +
                    ((ntp * 16 + rkb) * AST + ks * 16 + kkb) * 2;
                ldsm4(r0, r1, r2, r3, addr);
                unsigned b0[2] = {r0, r1}, b1[2] = {r2, r3};
#pragma unroll
                for (int mi = 0; mi < 2; mi++) {
                    mma16816(sc[mi][2 * ntp],     qa[mi][ks], b0);
                    mma16816(sc[mi][2 * ntp + 1], qa[mi][ks], b1);
                }
            }
        }

        // online softmax per mi group (rows g and g+8; 4 lanes per row)
        unsigned ph[2][8][2];
#pragma unroll
        for (int mi = 0; mi < 2; mi++) {
            float mt0 = -3.0e38f, mt1 = -3.0e38f;
#pragma unroll
            for (int ni = 0; ni < 8; ni++) {
                mt0 = fmaxf(mt0, fmaxf(sc[mi][ni][0], sc[mi][ni][1]));
                mt1 = fmaxf(mt1, fmaxf(sc[mi][ni][2], sc[mi][ni][3]));
            }
            mt0 = fmaxf(mt0, __shfl_xor_sync(0xffffffffu, mt0, 1));
            mt0 = fmaxf(mt0, __shfl_xor_sync(0xffffffffu, mt0, 2));
            mt1 = fmaxf(mt1, __shfl_xor_sync(0xffffffffu, mt1, 1));
            mt1 = fmaxf(mt1, __shfl_xor_sync(0xffffffffu, mt1, 2));

            const float mn0 = fmaxf(mv0[mi], mt0), mn1 = fmaxf(mv1[mi], mt1);
            const float a0 = exp2f(mv0[mi] - mn0), a1 = exp2f(mv1[mi] - mn1);
            mv0[mi] = mn0; mv1[mi] = mn1;
            lv0[mi] *= a0; lv1[mi] *= a1;
#pragma unroll
            for (int ni = 0; ni < 8; ni++) {
                o[mi][ni][0] *= a0; o[mi][ni][1] *= a0;
                o[mi][ni][2] *= a1; o[mi][ni][3] *= a1;
            }

            float s0 = 0.0f, s1 = 0.0f;
#pragma unroll
            for (int ni = 0; ni < 8; ni++) {
                const float p0 = exp2f(sc[mi][ni][0] - mn0);
                const float p1 = exp2f(sc[mi][ni][1] - mn0);
                const float p2 = exp2f(sc[mi][ni][2] - mn1);
                const float p3 = exp2f(sc[mi][ni][3] - mn1);
                s0 += p0 + p1; s1 += p2 + p3;
                __half2 h0 = __floats2half2_rn(p0, p1);
                __half2 h1 = __floats2half2_rn(p2, p3);
                ph[mi][ni][0] = *(unsigned*)&h0;
                ph[mi][ni][1] = *(unsigned*)&h1;
            }
            s0 += __shfl_xor_sync(0xffffffffu, s0, 1);
            s0 += __shfl_xor_sync(0xffffffffu, s0, 2);
            s1 += __shfl_xor_sync(0xffffffffu, s1, 1);
            s1 += __shfl_xor_sync(0xffffffffu, s1, 2);
            lv0[mi] += s0; lv1[mi] += s1;
        }

        // O += P V : V B-frags shared across both mi groups (f32 acc)
#pragma unroll
        for (int ks = 0; ks < 4; ks++) {
#pragma unroll
            for (int ntp = 0; ntp < 4; ntp++) {
                unsigned r0, r1, r2, r3;
                const unsigned addr = sV + stg * ABUF +
                    ((ks * 16 + rvb) * AST + ntp * 16 + kvb) * 2;
                ldsm4t(r0, r1, r2, r3, addr);
                unsigned b0[2] = {r0, r1}, b1[2] = {r2, r3};
#pragma unroll
                for (int mi = 0; mi < 2; mi++) {
                    unsigned pa[4];
                    pa[0] = ph[mi][2 * ks][0];
                    pa[1] = ph[mi][2 * ks][1];
                    pa[2] = ph[mi][2 * ks + 1][0];
                    pa[3] = ph[mi][2 * ks + 1][1];
                    mma16816(o[mi][2 * ntp],     pa, b0);
                    mma16816(o[mi][2 * ntp + 1], pa, b1);
                }
            }
        }
    }

    // epilogue: normalize, write fp16 to g_attnh [B*S][D]
    const int b = bh >> 4, h = bh & (H_ - 1);
#pragma unroll
    for (int mi = 0; mi < 2; mi++) {
        const float i0 = 1.0f / lv0[mi], i1 = 1.0f / lv1[mi];
        __half* O0 = g_attnh + (size_t)(b * S_ + q0 + wq + mi * 16 + g) * D_ + h * HD_;
        __half* O1 = g_attnh + (size_t)(b * S_ + q0 + wq + mi * 16 + g + 8) * D_ + h * HD_;
#pragma unroll
        for (int ni = 0; ni < 8; ni++) {
            const int c = ni * 8 + 2 * tg;
            *(__half2*)(O0 + c) = __floats2half2_rn(o[mi][ni][0] * i0, o[mi][ni][1] * i0);
            *(__half2*)(O1 + c) = __floats2half2_rn(o[mi][ni][2] * i1, o[mi][ni][3] * i1);
        }
    }
}

// ---------------------------------------------------------------------------
extern "C" void kernel_launch(void* const* d_in, const int* in_sizes, int n_in,
                              void* d_out, int out_size)
{
    const float* x      = (const float*)d_in[0];
    const float* w_qkv  = (const float*)d_in[1];
    const float* b_qkv  = (const float*)d_in[2];
    const float* w_proj = (const float*)d_in[3];
    const float* b_proj = (const float*)d_in[4];
    float* out = (float*)d_out;

    __half *xh, *wqkvh, *wprojh;
    cudaGetSymbolAddress((void**)&xh,     g_xh);
    cudaGetSymbolAddress((void**)&wqkvh,  g_wqkvh);
    cudaGetSymbolAddress((void**)&wprojh, g_wprojh);

    cudaFuncSetAttribute((const void*)gemm_h<1, 128, 2, 3>,
                         cudaFuncAttributeMaxDynamicSharedMemorySize, GSMEM(128, 2));
    cudaFuncSetAttribute((const void*)gemm_h<0, 64, 2, 4>,
                         cudaFuncAttributeMaxDynamicSharedMemorySize, GSMEM(64, 2));
    cudaFuncSetAttribute((const void*)attn_h,
                         cudaFuncAttributeMaxDynamicSharedMemorySize, ASMEM);

    // 0) fp32 -> fp16 (single launch)
    cvt_all<<<(N1_ + N2_ + N3_) / 4 / 256, 256>>>(x, w_qkv, w_proj);

    // 1) QKV projection -> g_qkvh [3,B,H,S,hd] (fp16): 2-stage, 3 CTAs/SM
    dim3 g1((3 * D_) / 128, M_ / 128);   // (24, 32)
    gemm_h<1, 128, 2, 3><<<g1, 128, GSMEM(128, 2)>>>(xh, wqkvh, b_qkv, nullptr, 3 * D_, D_);

    // 2) attention -> g_attnh [B,S,D] (fp16): Q pre-scaled at load
    attn_h<<<dim3(S_ / 128, B_ * H_), 128, ASMEM>>>();

    // 3) output projection -> d_out (fp32): BM=64, 2-stage, 4 CTAs/SM
    dim3 g2(D_ / 128, M_ / 64);          // (8, 64)
    gemm_h<0, 64, 2, 4><<<g2, 128, GSMEM(64, 2)>>>(nullptr, wprojh, b_proj, out, D_, D_);
}